// round 1
// baseline (speedup 1.0000x reference)
#include <cuda_runtime.h>
#include <cuda_bf16.h>
#include <cstdint>

// Problem constants
#define NN 512
#define CC 512
#define HH 14
#define WW 14
#define HW 196              // 14*14
#define CHW 100352          // 512*196
#define KV4 25088           // CHW/4 (float4 count per image)
#define ROI 49              // 7*7
#define RROWS 490           // 10*49 folded rows
#define TOUT 10             // 2 note + 8 reg outputs
#define SPLITS 4
#define CH4 6272            // KV4/SPLITS
#define NTILE 4

// ---------------- device scratch (no allocations allowed) ----------------
__device__ __align__(16) float g_U  [RROWS * CC];
__device__ __align__(16) float g_G3 [RROWS * CC];
__device__ __align__(16) float g_G2 [RROWS * CC];
__device__ __align__(16) float g_G1 [RROWS * CC];
__device__ __align__(16) float g_R  [ROI * HW];
__device__ __align__(16) float g_Bsp[TOUT * CHW];
__device__ float g_beta2[CC];
__device__ float g_beta3[CC];
__device__ float g_bconst[TOUT];
__device__ float g_part[SPLITS * NN * TOUT];

// ---------------- 1. gather U[r,o] = w_{note,reg}[t, o*49+p] ----------------
__global__ void build_u(const float* __restrict__ wn, const float* __restrict__ wr) {
    int idx = blockIdx.x * blockDim.x + threadIdx.x;
    if (idx >= RROWS * CC) return;
    int r = idx / CC, o = idx % CC;
    int t = r / ROI, p = r % ROI;
    float v = (t < 2) ? wn[t * (CC * ROI) + o * ROI + p]
                      : wr[(t - 2) * (CC * ROI) + o * ROI + p];
    g_U[r * CC + o] = v;
}

// ---------------- 2. tiled fp32 GEMM  C[M,N] = A[M,K] * B[K,N] ----------------
#define BM 32
#define BN 64
#define BK 16
__global__ __launch_bounds__(256) void gemm_kernel(
    const float* __restrict__ A, const float* __restrict__ B,
    float* __restrict__ C, int M, int N, int K)
{
    __shared__ float As[BK][BM];
    __shared__ float Bs[BK][BN];
    int tid = threadIdx.x;
    int m0 = blockIdx.y * BM;
    int n0 = blockIdx.x * BN;
    int ty = tid >> 4;          // 0..15
    int tx = tid & 15;          // 0..15
    float acc[2][4] = {};
    for (int k0 = 0; k0 < K; k0 += BK) {
        #pragma unroll
        for (int i = 0; i < 2; i++) {
            int e = tid + i * 256;      // 0..511
            int m = e >> 4;
            int k = e & 15;
            float v = 0.f;
            if (m0 + m < M) v = A[(m0 + m) * K + k0 + k];
            As[k][m] = v;
        }
        {
            int k  = tid >> 4;          // 0..15
            int n4 = (tid & 15) * 4;    // 0..60
            float4 v = *reinterpret_cast<const float4*>(&B[(k0 + k) * N + n0 + n4]);
            *reinterpret_cast<float4*>(&Bs[k][n4]) = v;
        }
        __syncthreads();
        #pragma unroll
        for (int k = 0; k < BK; k++) {
            float a0 = As[k][ty * 2];
            float a1 = As[k][ty * 2 + 1];
            float b0 = Bs[k][tx * 4 + 0];
            float b1 = Bs[k][tx * 4 + 1];
            float b2 = Bs[k][tx * 4 + 2];
            float b3 = Bs[k][tx * 4 + 3];
            acc[0][0] += a0 * b0; acc[0][1] += a0 * b1;
            acc[0][2] += a0 * b2; acc[0][3] += a0 * b3;
            acc[1][0] += a1 * b0; acc[1][1] += a1 * b1;
            acc[1][2] += a1 * b2; acc[1][3] += a1 * b3;
        }
        __syncthreads();
    }
    #pragma unroll
    for (int i = 0; i < 2; i++) {
        int m = m0 + ty * 2 + i;
        if (m < M) {
            #pragma unroll
            for (int j = 0; j < 4; j++)
                C[m * N + n0 + tx * 4 + j] = acc[i][j];
        }
    }
}

// ---------------- 3. fixed RoIAlign operator R[p,hw] ----------------
__global__ void build_r() {
    int p  = blockIdx.x;      // 49
    int hw = threadIdx.x;     // 196
    int i = p / 7, j = p % 7;
    const float base = 3.0f / 7.0f;
    const float step = 13.0f / 7.0f;
    float yc = base + i * step;
    float xc = base + j * step;
    float y0f = floorf(yc), x0f = floorf(xc);
    float wy = yc - y0f, wx = xc - x0f;
    int y0 = min(max((int)y0f, 0), HH - 1);
    int y1 = min(y0 + 1, HH - 1);
    int x0 = min(max((int)x0f, 0), WW - 1);
    int x1 = min(x0 + 1, WW - 1);
    int y = hw / WW, x = hw % WW;
    float v = 0.f;
    if (y == y0 && x == x0) v += (1.f - wy) * (1.f - wx);
    if (y == y0 && x == x1) v += (1.f - wy) * wx;
    if (y == y1 && x == x0) v += wy * (1.f - wx);
    if (y == y1 && x == x1) v += wy * wx;
    g_R[p * HW + hw] = v;
}

// ---------------- 4. Bsp[t,c,hw] = sum_p G1[t*49+p, c] * R[p,hw] ----------------
__global__ void build_bsp() {
    int c  = blockIdx.x;   // 512
    int t  = blockIdx.y;   // 10
    int hw = threadIdx.x;  // 196
    float acc = 0.f;
    #pragma unroll
    for (int p = 0; p < ROI; p++)
        acc += g_G1[(t * ROI + p) * CC + c] * g_R[p * HW + hw];
    g_Bsp[(t * CC + c) * HW + hw] = acc;
}

// ---------------- 5. bias chain (b1,b2,b3 are zeros, but handle generally) ----
__global__ void matvec512(const float* __restrict__ W, const float* __restrict__ v,
                          const float* __restrict__ b, float* __restrict__ out) {
    int i = blockIdx.x;       // 512
    int lane = threadIdx.x;   // 32
    float s = 0.f;
    for (int k = lane; k < CC; k += 32) s += W[i * CC + k] * v[k];
    #pragma unroll
    for (int o = 16; o; o >>= 1) s += __shfl_down_sync(0xffffffffu, s, o);
    if (lane == 0) out[i] = s + b[i];
}

__global__ void bias_final(const float* __restrict__ wn, const float* __restrict__ wr,
                           const float* __restrict__ bn, const float* __restrict__ br) {
    int t = blockIdx.x;       // 10
    const float* w = (t < 2) ? wn + t * (CC * ROI) : wr + (t - 2) * (CC * ROI);
    float s = 0.f;
    for (int i = threadIdx.x; i < CC * ROI; i += 256) s += w[i] * g_beta3[i / ROI];
    int lane = threadIdx.x & 31, warp = threadIdx.x >> 5;
    #pragma unroll
    for (int o = 16; o; o >>= 1) s += __shfl_down_sync(0xffffffffu, s, o);
    __shared__ float red[8];
    if (lane == 0) red[warp] = s;
    __syncthreads();
    if (threadIdx.x == 0) {
        float tot = 0.f;
        #pragma unroll
        for (int w8 = 0; w8 < 8; w8++) tot += red[w8];
        g_bconst[t] = tot + ((t < 2) ? bn[t] : br[t - 2]);
    }
}

// ---------------- 6. main HBM-bound pass: out[n,t] += <Bsp[t], proj[n]> ------
__global__ __launch_bounds__(256) void main_gemm(const float* __restrict__ proj) {
    int n0 = blockIdx.x * NTILE;          // 128 groups of 4 images
    int sc = blockIdx.y;                  // 4 K-splits
    int tid = threadIdx.x;
    const float4* P  = reinterpret_cast<const float4*>(proj) + (size_t)n0 * KV4;
    const float4* Bv = reinterpret_cast<const float4*>(g_Bsp);

    float acc[NTILE][TOUT];
    #pragma unroll
    for (int j = 0; j < NTILE; j++)
        #pragma unroll
        for (int t = 0; t < TOUT; t++) acc[j][t] = 0.f;

    int base = sc * CH4;
    for (int k = tid; k < CH4; k += 256) {
        int idx = base + k;
        float4 p0 = P[0 * KV4 + idx];
        float4 p1 = P[1 * KV4 + idx];
        float4 p2 = P[2 * KV4 + idx];
        float4 p3 = P[3 * KV4 + idx];
        #pragma unroll
        for (int t = 0; t < TOUT; t++) {
            float4 b = Bv[t * KV4 + idx];
            acc[0][t] += p0.x * b.x + p0.y * b.y + p0.z * b.z + p0.w * b.w;
            acc[1][t] += p1.x * b.x + p1.y * b.y + p1.z * b.z + p1.w * b.w;
            acc[2][t] += p2.x * b.x + p2.y * b.y + p2.z * b.z + p2.w * b.w;
            acc[3][t] += p3.x * b.x + p3.y * b.y + p3.z * b.z + p3.w * b.w;
        }
    }

    // block reduction of 40 partials
    int lane = tid & 31, warp = tid >> 5;
    __shared__ float red[8][NTILE * TOUT];
    #pragma unroll
    for (int j = 0; j < NTILE; j++) {
        #pragma unroll
        for (int t = 0; t < TOUT; t++) {
            float v = acc[j][t];
            v += __shfl_down_sync(0xffffffffu, v, 16);
            v += __shfl_down_sync(0xffffffffu, v, 8);
            v += __shfl_down_sync(0xffffffffu, v, 4);
            v += __shfl_down_sync(0xffffffffu, v, 2);
            v += __shfl_down_sync(0xffffffffu, v, 1);
            if (lane == 0) red[warp][j * TOUT + t] = v;
        }
    }
    __syncthreads();
    if (tid < NTILE * TOUT) {
        float v = 0.f;
        #pragma unroll
        for (int w8 = 0; w8 < 8; w8++) v += red[w8][tid];
        int j = tid / TOUT, t = tid % TOUT;
        g_part[((size_t)sc * NN + n0 + j) * TOUT + t] = v;
    }
}

// ---------------- 7. finalize: reduce splits, add bias, scatter to layout ----
__global__ void finalize(float* __restrict__ out) {
    int idx = blockIdx.x * blockDim.x + threadIdx.x;
    if (idx >= NN * TOUT) return;
    int n = idx / TOUT, t = idx % TOUT;
    float v = g_bconst[t];
    #pragma unroll
    for (int sc = 0; sc < SPLITS; sc++)
        v += g_part[((size_t)sc * NN + n) * TOUT + t];
    if (t < 2) out[n * 2 + t] = v;                 // note [512,2]
    else       out[NN * 2 + n * 8 + (t - 2)] = v;  // reg  [512,8]
}

// ---------------- launch ----------------
extern "C" void kernel_launch(void* const* d_in, const int* in_sizes, int n_in,
                              void* d_out, int out_size) {
    const float* project = (const float*)d_in[0];
    const float* w1      = (const float*)d_in[1];
    const float* b1      = (const float*)d_in[2];
    const float* w2      = (const float*)d_in[3];
    const float* b2      = (const float*)d_in[4];
    const float* w3      = (const float*)d_in[5];
    const float* b3      = (const float*)d_in[6];
    const float* w_note  = (const float*)d_in[7];
    const float* b_note  = (const float*)d_in[8];
    const float* w_reg   = (const float*)d_in[9];
    const float* b_reg   = (const float*)d_in[10];
    float* out = (float*)d_out;

    float *pU, *pG3, *pG2, *pG1, *pb2, *pb3;
    cudaGetSymbolAddress((void**)&pU,  g_U);
    cudaGetSymbolAddress((void**)&pG3, g_G3);
    cudaGetSymbolAddress((void**)&pG2, g_G2);
    cudaGetSymbolAddress((void**)&pG1, g_G1);
    cudaGetSymbolAddress((void**)&pb2, g_beta2);
    cudaGetSymbolAddress((void**)&pb3, g_beta3);

    // fold weights: G1 = ((U*w3)*w2)*w1
    build_u<<<(RROWS * CC + 255) / 256, 256>>>(w_note, w_reg);
    dim3 gg(CC / BN, (RROWS + BM - 1) / BM);
    gemm_kernel<<<gg, 256>>>(pU,  w3, pG3, RROWS, CC, CC);
    gemm_kernel<<<gg, 256>>>(pG3, w2, pG2, RROWS, CC, CC);
    gemm_kernel<<<gg, 256>>>(pG2, w1, pG1, RROWS, CC, CC);

    // fixed RoI operator and spatial fold
    build_r<<<ROI, HW>>>();
    build_bsp<<<dim3(CC, TOUT), HW>>>();

    // bias chain (zeros in this dataset, computed anyway for generality)
    matvec512<<<CC, 32>>>(w2, b1, b2, pb2);
    matvec512<<<CC, 32>>>(w3, pb2, b3, pb3);
    bias_final<<<TOUT, 256>>>(w_note, w_reg, b_note, b_reg);

    // main HBM-bound pass + finalize
    main_gemm<<<dim3(NN / NTILE, SPLITS), 256>>>(project);
    finalize<<<(NN * TOUT + 255) / 256, 256>>>(out);
}

// round 3
// speedup vs baseline: 1.2769x; 1.2769x over previous
#include <cuda_runtime.h>
#include <cuda_bf16.h>
#include <cstdint>

// Problem constants
#define NN 512
#define CC 512
#define HH 14
#define WW 14
#define HW 196
#define ROI 49
#define RROWS 490            // 10*49
#define TOUT 10
#define CHW 100352           // 512*196
#define KV4 25088            // CHW/4
#define SK 4                 // split-K for fold GEMMs
#define MSPLIT 4             // K splits for main pass
#define CHUNK4 6272          // KV4/MSPLIT
#define NTILE 16

#define T1E (RROWS * CC)     // 250880
#define T2E (CC * CC)        // 262144

// ---------------- device scratch ----------------
__device__ __align__(16) float g_U  [T1E];
__device__ __align__(16) float g_T1p[SK * T1E];
__device__ __align__(16) float g_T2p[SK * T2E];
__device__ __align__(16) float g_T1r[T1E];
__device__ __align__(16) float g_T2r[T2E];
__device__ __align__(16) float g_G1p[SK * T1E];
__device__ __align__(16) float g_R  [ROI * HW];
__device__ __align__(16) float g_Bsp[TOUT * CHW];
__device__ float g_beta2[CC];
__device__ float g_beta3[CC];
__device__ float g_bconst[TOUT];
__device__ float g_part[MSPLIT * NN * TOUT];

// ---------------- 1. gather U[r,o] = heads[t, o*49+p] ----------------
__global__ void build_u(const float* __restrict__ wn, const float* __restrict__ wr) {
    int idx = blockIdx.x * blockDim.x + threadIdx.x;
    if (idx >= RROWS * CC) return;
    int r = idx / CC, o = idx % CC;
    int t = r / ROI, p = r % ROI;
    float v = (t < 2) ? wn[t * (CC * ROI) + o * ROI + p]
                      : wr[(t - 2) * (CC * ROI) + o * ROI + p];
    g_U[r * CC + o] = v;
}

// ---------------- 2. GEMM body: 64x64 tile, 4x4 reg block, K-chunk 128 ------
// C[m,n] = sum_{k in [kbase,kbase+128)} A[m,k]*B[k,n], N=K=512 fixed.
__device__ __forceinline__ void gemm_body(
    const float* __restrict__ A, const float* __restrict__ B,
    float* __restrict__ Cz, int M, int kbase)
{
    __shared__ float As[16][64];
    __shared__ float Bs[16][64];
    int tid = threadIdx.x;
    int m0 = blockIdx.y * 64;
    int n0 = blockIdx.x * 64;

    int ar  = tid >> 2;          // 0..63
    int acq = tid & 3;           // 0..3
    int bkr = tid >> 4;          // 0..15
    int bnc = (tid & 15) * 4;
    int ty  = tid >> 4;
    int tx  = tid & 15;

    float acc[4][4] = {};
    #pragma unroll 1
    for (int kk = 0; kk < 128; kk += 16) {
        int k0 = kbase + kk;
        float4 a4 = make_float4(0.f, 0.f, 0.f, 0.f);
        if (m0 + ar < M)
            a4 = *reinterpret_cast<const float4*>(&A[(size_t)(m0 + ar) * 512 + k0 + acq * 4]);
        As[acq * 4 + 0][ar] = a4.x;
        As[acq * 4 + 1][ar] = a4.y;
        As[acq * 4 + 2][ar] = a4.z;
        As[acq * 4 + 3][ar] = a4.w;
        *reinterpret_cast<float4*>(&Bs[bkr][bnc]) =
            *reinterpret_cast<const float4*>(&B[(size_t)(k0 + bkr) * 512 + n0 + bnc]);
        __syncthreads();
        #pragma unroll
        for (int k = 0; k < 16; k++) {
            float4 a = *reinterpret_cast<const float4*>(&As[k][ty * 4]);
            float4 b = *reinterpret_cast<const float4*>(&Bs[k][tx * 4]);
            acc[0][0] += a.x * b.x; acc[0][1] += a.x * b.y; acc[0][2] += a.x * b.z; acc[0][3] += a.x * b.w;
            acc[1][0] += a.y * b.x; acc[1][1] += a.y * b.y; acc[1][2] += a.y * b.z; acc[1][3] += a.y * b.w;
            acc[2][0] += a.z * b.x; acc[2][1] += a.z * b.y; acc[2][2] += a.z * b.z; acc[2][3] += a.z * b.w;
            acc[3][0] += a.w * b.x; acc[3][1] += a.w * b.y; acc[3][2] += a.w * b.z; acc[3][3] += a.w * b.w;
        }
        __syncthreads();
    }
    #pragma unroll
    for (int i = 0; i < 4; i++) {
        int m = m0 + ty * 4 + i;
        if (m < M) {
            float4 v = make_float4(acc[i][0], acc[i][1], acc[i][2], acc[i][3]);
            *reinterpret_cast<float4*>(&Cz[(size_t)m * 512 + n0 + tx * 4]) = v;
        }
    }
}

// one launch: z<SK -> T1 = U@w3 chunk, else T2 = w2@w1 chunk
__global__ __launch_bounds__(256) void gemm_fold1(
    const float* __restrict__ w3, const float* __restrict__ w2,
    const float* __restrict__ w1)
{
    int zz = blockIdx.z;
    int zk = zz & (SK - 1);
    if (zz < SK)
        gemm_body(g_U, w3, g_T1p + (size_t)zk * T1E, RROWS, zk * 128);
    else
        gemm_body(w2, w1, g_T2p + (size_t)zk * T2E, CC, zk * 128);
}

// G1p[z] = T1r @ T2r chunk
__global__ __launch_bounds__(256) void gemm_fold2() {
    int zk = blockIdx.z;
    gemm_body(g_T1r, g_T2r, g_G1p + (size_t)zk * T1E, RROWS, zk * 128);
}

// ---------------- 3. reduce split-K partials for T1 and T2 (vectorized) -----
__global__ void reduce_t() {
    int i = blockIdx.x * blockDim.x + threadIdx.x;
    const int T14 = T1E / 4;     // 62720
    const int T24 = T2E / 4;     // 65536
    if (i < T14) {
        const float4* a = reinterpret_cast<const float4*>(g_T1p);
        float4 v = a[i];
        #pragma unroll
        for (int s = 1; s < SK; s++) {
            float4 w = a[s * T14 + i];
            v.x += w.x; v.y += w.y; v.z += w.z; v.w += w.w;
        }
        reinterpret_cast<float4*>(g_T1r)[i] = v;
    } else if (i < T14 + T24) {
        int j = i - T14;
        const float4* a = reinterpret_cast<const float4*>(g_T2p);
        float4 v = a[j];
        #pragma unroll
        for (int s = 1; s < SK; s++) {
            float4 w = a[s * T24 + j];
            v.x += w.x; v.y += w.y; v.z += w.z; v.w += w.w;
        }
        reinterpret_cast<float4*>(g_T2r)[j] = v;
    }
}

// ---------------- 4. fixed RoIAlign operator R[p,hw] ----------------
__global__ void build_r() {
    int p  = blockIdx.x;
    int hw = threadIdx.x;
    int i = p / 7, j = p % 7;
    const float base = 3.0f / 7.0f;
    const float step = 13.0f / 7.0f;
    float yc = base + i * step;
    float xc = base + j * step;
    float y0f = floorf(yc), x0f = floorf(xc);
    float wy = yc - y0f, wx = xc - x0f;
    int y0 = min(max((int)y0f, 0), HH - 1);
    int y1 = min(y0 + 1, HH - 1);
    int x0 = min(max((int)x0f, 0), WW - 1);
    int x1 = min(x0 + 1, WW - 1);
    int y = hw / WW, x = hw % WW;
    float v = 0.f;
    if (y == y0 && x == x0) v += (1.f - wy) * (1.f - wx);
    if (y == y0 && x == x1) v += (1.f - wy) * wx;
    if (y == y1 && x == x0) v += wy * (1.f - wx);
    if (y == y1 && x == x1) v += wy * wx;
    g_R[p * HW + hw] = v;
}

// ---------------- 5. Bsp[t,c,hw] = sum_p (sum_s G1p[s])[t*49+p,c]*R[p,hw] ---
__global__ void build_bsp() {
    int c  = blockIdx.x;   // 512
    int t  = blockIdx.y;   // 10
    int hw = threadIdx.x;  // 196
    float acc = 0.f;
    #pragma unroll 7
    for (int p = 0; p < ROI; p++) {
        size_t gi = (size_t)(t * ROI + p) * CC + c;
        float g = g_G1p[gi];     // broadcast loads across the block
        #pragma unroll
        for (int s = 1; s < SK; s++) g += g_G1p[(size_t)s * T1E + gi];
        acc += g * g_R[p * HW + hw];
    }
    g_Bsp[(size_t)(t * CC + c) * HW + hw] = acc;
}

// ---------------- 6. bias chain ----------------
__global__ void matvec512(const float* __restrict__ W, const float* __restrict__ v,
                          const float* __restrict__ b, float* __restrict__ out) {
    int i = blockIdx.x;
    int lane = threadIdx.x;
    float s = 0.f;
    for (int k = lane; k < CC; k += 32) s += W[i * CC + k] * v[k];
    #pragma unroll
    for (int o = 16; o; o >>= 1) s += __shfl_down_sync(0xffffffffu, s, o);
    if (lane == 0) out[i] = s + b[i];
}

__global__ void bias_final(const float* __restrict__ wn, const float* __restrict__ wr,
                           const float* __restrict__ bn, const float* __restrict__ br) {
    int t = blockIdx.x;
    const float* w = (t < 2) ? wn + t * (CC * ROI) : wr + (t - 2) * (CC * ROI);
    float s = 0.f;
    for (int i = threadIdx.x; i < CC * ROI; i += 256) s += w[i] * g_beta3[i / ROI];
    int lane = threadIdx.x & 31, warp = threadIdx.x >> 5;
    #pragma unroll
    for (int o = 16; o; o >>= 1) s += __shfl_down_sync(0xffffffffu, s, o);
    __shared__ float red[8];
    if (lane == 0) red[warp] = s;
    __syncthreads();
    if (threadIdx.x == 0) {
        float tot = 0.f;
        #pragma unroll
        for (int w8 = 0; w8 < 8; w8++) tot += red[w8];
        g_bconst[t] = tot + ((t < 2) ? bn[t] : br[t - 2]);
    }
}

// ---------------- 7. main pass: 16 images/block, 10 outputs, split-K --------
__global__ __launch_bounds__(256) void main_gemm(const float* __restrict__ proj) {
    int n0 = blockIdx.x * NTILE;          // 32 groups of 16 images
    int sc = blockIdx.y;                  // 4 K-splits
    int tid = threadIdx.x;
    const float4* P  = reinterpret_cast<const float4*>(proj) + (size_t)n0 * KV4;
    const float4* Bv = reinterpret_cast<const float4*>(g_Bsp);

    float acc[NTILE][TOUT];
    #pragma unroll
    for (int j = 0; j < NTILE; j++)
        #pragma unroll
        for (int t = 0; t < TOUT; t++) acc[j][t] = 0.f;

    int base = sc * CHUNK4;
    for (int k = tid; k < CHUNK4; k += 256) {
        int idx = base + k;
        // half 1: outputs 0..4
        float4 b0 = Bv[0 * KV4 + idx];
        float4 b1 = Bv[1 * KV4 + idx];
        float4 b2 = Bv[2 * KV4 + idx];
        float4 b3 = Bv[3 * KV4 + idx];
        float4 b4 = Bv[4 * KV4 + idx];
        #pragma unroll
        for (int j = 0; j < NTILE; j++) {
            float4 p = P[(size_t)j * KV4 + idx];
            acc[j][0] += p.x * b0.x + p.y * b0.y + p.z * b0.z + p.w * b0.w;
            acc[j][1] += p.x * b1.x + p.y * b1.y + p.z * b1.z + p.w * b1.w;
            acc[j][2] += p.x * b2.x + p.y * b2.y + p.z * b2.z + p.w * b2.w;
            acc[j][3] += p.x * b3.x + p.y * b3.y + p.z * b3.z + p.w * b3.w;
            acc[j][4] += p.x * b4.x + p.y * b4.y + p.z * b4.z + p.w * b4.w;
        }
        // half 2: outputs 5..9 (p re-loads hit L1)
        b0 = Bv[5 * KV4 + idx];
        b1 = Bv[6 * KV4 + idx];
        b2 = Bv[7 * KV4 + idx];
        b3 = Bv[8 * KV4 + idx];
        b4 = Bv[9 * KV4 + idx];
        #pragma unroll
        for (int j = 0; j < NTILE; j++) {
            float4 p = P[(size_t)j * KV4 + idx];
            acc[j][5] += p.x * b0.x + p.y * b0.y + p.z * b0.z + p.w * b0.w;
            acc[j][6] += p.x * b1.x + p.y * b1.y + p.z * b1.z + p.w * b1.w;
            acc[j][7] += p.x * b2.x + p.y * b2.y + p.z * b2.z + p.w * b2.w;
            acc[j][8] += p.x * b3.x + p.y * b3.y + p.z * b3.z + p.w * b3.w;
            acc[j][9] += p.x * b4.x + p.y * b4.y + p.z * b4.z + p.w * b4.w;
        }
    }

    // block reduction of 160 partials
    int lane = tid & 31, warp = tid >> 5;
    __shared__ float red[8][NTILE * TOUT];
    #pragma unroll
    for (int j = 0; j < NTILE; j++) {
        #pragma unroll
        for (int t = 0; t < TOUT; t++) {
            float v = acc[j][t];
            v += __shfl_down_sync(0xffffffffu, v, 16);
            v += __shfl_down_sync(0xffffffffu, v, 8);
            v += __shfl_down_sync(0xffffffffu, v, 4);
            v += __shfl_down_sync(0xffffffffu, v, 2);
            v += __shfl_down_sync(0xffffffffu, v, 1);
            if (lane == 0) red[warp][j * TOUT + t] = v;
        }
    }
    __syncthreads();
    if (tid < NTILE * TOUT) {
        float v = 0.f;
        #pragma unroll
        for (int w8 = 0; w8 < 8; w8++) v += red[w8][tid];
        int j = tid / TOUT, t = tid % TOUT;
        g_part[((size_t)sc * NN + n0 + j) * TOUT + t] = v;
    }
}

// ---------------- 8. finalize ----------------
__global__ void finalize(float* __restrict__ out) {
    int idx = blockIdx.x * blockDim.x + threadIdx.x;
    if (idx >= NN * TOUT) return;
    int n = idx / TOUT, t = idx % TOUT;
    float v = g_bconst[t];
    #pragma unroll
    for (int sc = 0; sc < MSPLIT; sc++)
        v += g_part[((size_t)sc * NN + n) * TOUT + t];
    if (t < 2) out[n * 2 + t] = v;
    else       out[NN * 2 + n * 8 + (t - 2)] = v;
}

// ---------------- launch: single stream, graph-capturable -------------------
extern "C" void kernel_launch(void* const* d_in, const int* in_sizes, int n_in,
                              void* d_out, int out_size) {
    const float* project = (const float*)d_in[0];
    const float* w1      = (const float*)d_in[1];
    const float* b1      = (const float*)d_in[2];
    const float* w2      = (const float*)d_in[3];
    const float* b2      = (const float*)d_in[4];
    const float* w3      = (const float*)d_in[5];
    const float* b3      = (const float*)d_in[6];
    const float* w_note  = (const float*)d_in[7];
    const float* b_note  = (const float*)d_in[8];
    const float* w_reg   = (const float*)d_in[9];
    const float* b_reg   = (const float*)d_in[10];
    float* out = (float*)d_out;

    float *pb2, *pb3;
    cudaGetSymbolAddress((void**)&pb2, g_beta2);
    cudaGetSymbolAddress((void**)&pb3, g_beta3);

    // fold: U gather; T1=U@w3 and T2=w2@w1 in ONE launch; reduce; G1=T1@T2
    build_u<<<(RROWS * CC + 255) / 256, 256>>>(w_note, w_reg);
    gemm_fold1<<<dim3(8, 8, 2 * SK), 256>>>(w3, w2, w1);
    reduce_t<<<(T1E / 4 + T2E / 4 + 255) / 256, 256>>>();
    gemm_fold2<<<dim3(8, 8, SK), 256>>>();

    // spatial fold (sums G1 split-K partials inline)
    build_r<<<ROI, HW>>>();
    build_bsp<<<dim3(CC, TOUT), HW>>>();

    // bias chain
    matvec512<<<CC, 32>>>(w2, b1, b2, pb2);
    matvec512<<<CC, 32>>>(w3, pb2, b3, pb3);
    bias_final<<<TOUT, 256>>>(w_note, w_reg, b_note, b_reg);

    // main HBM-bound pass + finalize
    main_gemm<<<dim3(NN / NTILE, MSPLIT), 256>>>(project);
    finalize<<<(NN * TOUT + 255) / 256, 256>>>(out);
}